// round 14
// baseline (speedup 1.0000x reference)
#include <cuda_runtime.h>
#include <cstdint>
#include <cub/cub.cuh>

// ---------------------------------------------------------------------------
// ProposalLayer: B=4, A=9, H=50, W=76, FEAT_STRIDE=16
// pre-NMS topN = 6000, post-NMS topN = 300, nms thresh = 0.7
// R14 = R13 (84.5us) with:
//   - ALL 94 intra-chunk 64x64 suppression matrices precomputed in ONE
//     fully-parallel pass (48KB, aliased onto the dead keys region) instead
//     of inside the serial chunk loop -> loop body = kept-test + propagate
//   - kept-test widened to 16 groups (all 1024 threads)
//   - float4-vectorized score passes + uint4-vectorized SMEM init
// ---------------------------------------------------------------------------

#define BATCH     4
#define A_NUM     9
#define H_DIM     50
#define W_DIM     76
#define HW_DIM    (H_DIM * W_DIM)          // 3800
#define N_ANCH    (A_NUM * HW_DIM)         // 34200 (= 8550 float4, 16B-aligned)
#define PRE_TOPN  6000
#define POST_TOPN 300
#define NMS_TH    0.7f
#define NBUCKET   16384
#define CAP       8192
#define NTHREADS  1024
#define NCHUNK    94                        // ceil(6000/64)
#define KGROUPS   16                        // kept-test groups (1024 threads)

typedef unsigned long long u64;

// SMEM layout (dynamic), bytes:
//   [0      , 65536 )  keys     u64[8192]    (ALIAS: rows_all u64[6016] after decode)
//   [65536  , 131072)  hist     u32[16384]   (ALIAS: dies before boxes written)
//   [65536  , 161536)  boxes    float4[6000] (primed: z=x2+1, w=y2+1)
//   [161536 , 185536)  areas    float[6000]  (reference form)
//   [185536 , 190336)  kbox     float4[300]
//   [190336 , 191536)  karea    float[300]
//   [191536 , 192048)  (pad)
//   [192048 , 192112)  dead     uchar[64]
#define SM_KEYS   0
#define SM_HIST   65536
#define SM_BOXES  65536
#define SM_AREAS  161536
#define SM_KBOX   185536
#define SM_KAREA  190336
#define SM_DEAD   192048
#define SM_TOTAL  192112

// Precomputed generate_anchors(base=16, ratios={0.5,1,2}, scales={8,16,32})
__constant__ float c_anchors[A_NUM * 4] = {
    -84.f,  -40.f,   99.f,   55.f,
   -176.f,  -88.f,  191.f,  103.f,
   -360.f, -184.f,  375.f,  199.f,
    -56.f,  -56.f,   71.f,   71.f,
   -120.f, -120.f,  135.f,  135.f,
   -248.f, -248.f,  263.f,  263.f,
    -36.f,  -80.f,   51.f,   95.f,
    -80.f, -168.f,   95.f,  183.f,
   -168.f, -344.f,  183.f,  359.f
};

// Descending value-bucket: monotone non-decreasing in descending-score order;
// coarse order exact, within-bucket order fixed by the full 46-bit key.
__device__ __forceinline__ int score_bucket(float sc) {
    int f = (int)(sc * (float)NBUCKET);
    f = min(max(f, 0), NBUCKET - 1);
    return (NBUCKET - 1) - f;
}

// Guard-banded IoU > 0.7 on PRIMED boxes (z=x2+1, w=y2+1). iw/ih bit-identical
// to reference (fl monotone: min(fl(a+1),fl(b+1)) == fl(min(a,b)+1)); areas
// are reference-form, so the exact fallback divides identical values.
__device__ __forceinline__ bool iou_sup(float4 p, float ap, float4 q, float aq) {
    float iw = fminf(p.z, q.z) - fmaxf(p.x, q.x);
    float ih = fminf(p.w, q.w) - fmaxf(p.y, q.y);
    float inter = fmaxf(iw, 0.0f) * fmaxf(ih, 0.0f);
    float u = ap + aq - inter;
    float diff = inter - NMS_TH * u;
    if (fabsf(diff) > 1e-5f * u) return diff > 0.0f;
    return (inter / u) > NMS_TH;
}

__global__ void __launch_bounds__(NTHREADS, 1)
proposal_kernel(const float* __restrict__ scores,
                const float* __restrict__ deltas,
                const float* __restrict__ im_info,
                float* __restrict__ out)
{
    const unsigned FULL = 0xFFFFFFFFu;
    int b = blockIdx.x;
    int t = threadIdx.x;
    extern __shared__ unsigned char sm[];
    u64*           keys  = (u64*)(sm + SM_KEYS);
    unsigned*      hist  = (unsigned*)(sm + SM_HIST);
    float4*        boxes = (float4*)(sm + SM_BOXES);
    float*         areas = (float*)(sm + SM_AREAS);
    float4*        kbox  = (float4*)(sm + SM_KBOX);
    float*         karea = (float*)(sm + SM_KAREA);
    unsigned char* dead  = (unsigned char*)(sm + SM_DEAD);
    volatile unsigned char* vdead = (volatile unsigned char*)dead;
    __shared__ int s_Bstar, s_cnt;
    __shared__ typename cub::BlockScan<unsigned, NTHREADS>::TempStorage scan_ts;

    // Pre-fill output rows: [b, 0,0,0,0] (d_out arrives poisoned).
    for (int j = t; j < POST_TOPN * 5; j += NTHREADS) {
        int r = j / 5, cc = j % 5;
        out[((size_t)b * POST_TOPN + r) * 5 + cc] = (cc == 0) ? (float)b : 0.0f;
    }

    // ===================== Phase 1: select top-6000 =========================
    {   // vectorized init: hist zero + keys ~0
        uint4 z4 = make_uint4(0, 0, 0, 0);
        uint4 f4 = make_uint4(~0u, ~0u, ~0u, ~0u);
        uint4* h4 = (uint4*)hist;
        uint4* k4 = (uint4*)keys;
        for (int q = t; q < NBUCKET / 4; q += NTHREADS) h4[q] = z4;
        for (int q = t; q < CAP * 2 / 4; q += NTHREADS) k4[q] = f4;
    }
    __syncthreads();

    const float*  sc_base = scores + ((size_t)b * 2 * A_NUM + A_NUM) * HW_DIM;
    const float4* sc4     = (const float4*)sc_base;     // 16B-aligned, 8550 vecs

    // Pass A: value-bucket histogram (float4 loads)
    for (int m4 = t; m4 < N_ANCH / 4; m4 += NTHREADS) {
        float4 s = sc4[m4];
        atomicAdd(&hist[score_bucket(s.x)], 1u);
        atomicAdd(&hist[score_bucket(s.y)], 1u);
        atomicAdd(&hist[score_bucket(s.z)], 1u);
        atomicAdd(&hist[score_bucket(s.w)], 1u);
    }
    __syncthreads();

    // Exclusive scan over buckets; find cutoff bucket B*.
    unsigned cnt16[16], sum = 0;
    #pragma unroll
    for (int k = 0; k < 16; k++) { cnt16[k] = hist[t * 16 + k]; sum += cnt16[k]; }
    unsigned ex_base;
    cub::BlockScan<unsigned, NTHREADS>(scan_ts).ExclusiveSum(sum, ex_base);
    unsigned run = ex_base;
    #pragma unroll
    for (int k = 0; k < 16; k++) {
        unsigned inc = run + cnt16[k];
        if (run < PRE_TOPN && inc >= PRE_TOPN) s_Bstar = t * 16 + k;
        hist[t * 16 + k] = run;
        run = inc;
    }
    __syncthreads();
    int Bstar = s_Bstar;

    // Pass B: scatter selected keys to their global-rank slot (float4 loads).
    for (int m4 = t; m4 < N_ANCH / 4; m4 += NTHREADS) {
        float4 s = sc4[m4];
        float sv[4] = {s.x, s.y, s.z, s.w};
        #pragma unroll
        for (int e = 0; e < 4; e++) {
            int bkt = score_bucket(sv[e]);
            if (bkt <= Bstar) {
                int m = m4 * 4 + e;
                unsigned u = __float_as_uint(sv[e]);
                u = min(u, 0x3F7FFFFFu);
                unsigned d = 0x3F7FFFFFu - u;
                int a = m / HW_DIM, hw = m - a * HW_DIM;
                unsigned idx = (unsigned)(hw * A_NUM + a);   // reference flatten
                int slot = (int)atomicAdd(&hist[bkt], 1u);
                if (slot < CAP) keys[slot] = ((u64)d << 16) | idx;
            }
        }
    }
    __syncthreads();

    // Per-bucket insertion sort by full key (spans ~Poisson(2.1)).
    for (int q = t; q <= Bstar; q += NTHREADS) {
        int start = (q == 0) ? 0 : (int)hist[q - 1];
        int end   = (int)hist[q];
        if (end > CAP) end = CAP;
        for (int x = start + 1; x < end; x++) {
            u64 kx = keys[x];
            int y = x - 1;
            while (y >= start && keys[y] > kx) { keys[y + 1] = keys[y]; y--; }
            keys[y + 1] = kx;
        }
    }
    __syncthreads();   // hist dead from here; boxes region may be written

    // ===================== Phase 2: decode into SMEM ========================
    float imh = im_info[b * 3 + 0];
    float imw = im_info[b * 3 + 1];
    const float* dl = deltas + (size_t)b * 4 * A_NUM * HW_DIM;

    for (int p = t; p < PRE_TOPN; p += NTHREADS) {
        unsigned idx = (unsigned)(keys[p] & 0xFFFFull);
        int a  = idx % A_NUM;
        int hw = idx / A_NUM;
        int w  = hw % W_DIM;
        int h  = hw / W_DIM;

        float sx = (float)(w * 16);
        float sy = (float)(h * 16);
        float ax1 = c_anchors[a * 4 + 0] + sx;
        float ay1 = c_anchors[a * 4 + 1] + sy;
        float ax2 = c_anchors[a * 4 + 2] + sx;
        float ay2 = c_anchors[a * 4 + 3] + sy;

        float wa  = ax2 - ax1 + 1.0f;
        float ha  = ay2 - ay1 + 1.0f;
        float cxa = ax1 + 0.5f * wa;
        float cya = ay1 + 0.5f * ha;

        size_t dbase = (size_t)(a * 4) * HW_DIM + hw;
        float dx = dl[dbase];
        float dy = dl[dbase +     HW_DIM];
        float dw = dl[dbase + 2 * HW_DIM];
        float dh = dl[dbase + 3 * HW_DIM];

        float pcx = dx * wa + cxa;
        float pcy = dy * ha + cya;
        float pw  = expf(dw) * wa;
        float ph  = expf(dh) * ha;

        float x1 = fminf(fmaxf(pcx - 0.5f * pw, 0.0f), imw - 1.0f);
        float y1 = fminf(fmaxf(pcy - 0.5f * ph, 0.0f), imh - 1.0f);
        float x2 = fminf(fmaxf(pcx + 0.5f * pw, 0.0f), imw - 1.0f);
        float y2 = fminf(fmaxf(pcy + 0.5f * ph, 0.0f), imh - 1.0f);

        // reference-form area FIRST, then primed box (monotone-rounded +1)
        areas[p] = (x2 - x1 + 1.0f) * (y2 - y1 + 1.0f);
        boxes[p] = make_float4(x1, y1, x2 + 1.0f, y2 + 1.0f);
    }
    if (t == 0) s_cnt = 0;
    __syncthreads();   // keys dead from here; rows_all may be written

    // ============ Phase 2b: precompute ALL intra-chunk matrices =============
    // rows_all[c*64 + r] = 64-bit suppression row of candidate r within chunk
    // c (bit j2 set iff IoU(r, j2) > 0.7, j2 > r). Depends only on boxes —
    // computed ONCE, fully parallel, off the serial chunk loop.
    u64* rows_all = (u64*)(sm + SM_KEYS);     // aliases dead keys region
    for (int idx = t; idx < NCHUNK * 64; idx += NTHREADS) {
        int c    = idx >> 6;
        int r    = idx & 63;
        int base = c << 6;
        int nvalid = min(64, PRE_TOPN - base);
        u64 bits = 0;
        if (r < nvalid - 1) {
            float4 b1 = boxes[base + r];
            float  a1 = areas[base + r];
            for (int j2 = r + 1; j2 < nvalid; j2++) {
                if (iou_sup(b1, a1, boxes[base + j2], areas[base + j2]))
                    bits |= 1ull << j2;
            }
        }
        rows_all[idx] = bits;
    }
    __syncthreads();

    // ===================== Phase 3: chunked greedy NMS ======================
    // Serial loop body is now ONLY: kept-list test (16 groups of 64, with
    // cross-group early-abort via dead[] polling) + t0 bit-propagation using
    // the precomputed matrix. Exactly reproduces greedy NMS order.
    for (int c = 0; c < NCHUNK; c++) {
        int base   = c << 6;
        int nvalid = min(64, PRE_TOPN - base);
        if (t < 64) dead[t] = (t >= nvalid) ? 1 : 0;
        __syncthreads();                       // S1: dead reset + s_cnt visible
        int kc = s_cnt;

        if (kc > 0) {
            // kept-test: group g (= t>>6) tests kept indices g, g+16, g+32...
            // for candidate j = t&63; dead[] poll pipelined ahead of each IoU.
            int j   = t & 63;
            int grp = t >> 6;
            if (j < nvalid) {
                float4 bj = boxes[base + j];
                float  aj = areas[base + j];
                for (int k = grp; k < kc; k += KGROUPS) {
                    unsigned char d = vdead[j];          // overlaps IoU math
                    if (iou_sup(kbox[k], karea[k], bj, aj)) { dead[j] = 1; break; }
                    if (d) break;
                }
            }
        }
        __syncthreads();                       // S2

        if (t < 32) {
            unsigned lo = __ballot_sync(FULL, dead[t]      == 0);
            unsigned hi = __ballot_sync(FULL, dead[t + 32] == 0);
            if (t == 0) {
                u64 alive = (u64)lo | ((u64)hi << 32);
                int cnt = s_cnt;
                while (alive && cnt < POST_TOPN) {
                    int j = __ffsll((long long)alive) - 1;
                    kbox[cnt]  = boxes[base + j];
                    karea[cnt] = areas[base + j];
                    cnt++;
                    alive &= ~(rows_all[base + j] | (1ull << j));
                }
                s_cnt = cnt;
            }
        }
        __syncthreads();                       // S3
        if (s_cnt >= POST_TOPN) break;
    }

    // ===================== Emit kept boxes (un-prime x2,y2) =================
    int total = s_cnt;
    for (int k = t; k < total; k += NTHREADS) {
        float4 v = kbox[k];
        float* o = out + ((size_t)b * POST_TOPN + k) * 5;
        o[1] = v.x; o[2] = v.y; o[3] = v.z - 1.0f; o[4] = v.w - 1.0f;
    }
}

// ---------------------------------------------------------------------------
// Launch: ONE kernel, one CTA per image.
// ---------------------------------------------------------------------------
extern "C" void kernel_launch(void* const* d_in, const int* in_sizes, int n_in,
                              void* d_out, int out_size)
{
    const float* scores  = (const float*)d_in[0];   // (4, 18, 50, 76)
    const float* deltas  = (const float*)d_in[1];   // (4, 36, 50, 76)
    const float* im_info = (const float*)d_in[2];   // (4, 3)
    float*       out     = (float*)d_out;           // (4, 300, 5)

    cudaFuncSetAttribute(proposal_kernel,
                         cudaFuncAttributeMaxDynamicSharedMemorySize,
                         SM_TOTAL);
    proposal_kernel<<<BATCH, NTHREADS, SM_TOTAL>>>(scores, deltas, im_info, out);
}

// round 15
// speedup vs baseline: 1.5958x; 1.5958x over previous
#include <cuda_runtime.h>
#include <cstdint>
#include <cub/cub.cuh>

// ---------------------------------------------------------------------------
// ProposalLayer: B=4, A=9, H=50, W=76, FEAT_STRIDE=16
// pre-NMS topN = 6000, post-NMS topN = 300, nms thresh = 0.7
// R15 = R13 NMS (proven 84.5us form) + thresholded histogram:
//   Pass A only histograms buckets < bucket(0.79) (~7.2K of 34.2K elements;
//   ATOMS 2cyc/lane serialization was ~45us of the select phase). Exact
//   counts for every bucket that can contain the 6000-cutoff; fail-closed
//   fallback to a full histogram if the crossing isn't found (untrusted
//   inputs). Plus float4 score loads and uint4 SMEM init.
// ---------------------------------------------------------------------------

#define BATCH     4
#define A_NUM     9
#define H_DIM     50
#define W_DIM     76
#define HW_DIM    (H_DIM * W_DIM)          // 3800
#define N_ANCH    (A_NUM * HW_DIM)         // 34200 (= 8550 float4, 16B-aligned)
#define PRE_TOPN  6000
#define POST_TOPN 300
#define NMS_TH    0.7f
#define NBUCKET   16384
#define CAP       8192
#define NTHREADS  1024
#define NCHUNK    94                        // ceil(6000/64)
#define KGROUPS   12                        // kept-test groups (768 threads)
#define SC_THRESH 0.79f                     // conservative top-6000 cutoff guess

typedef unsigned long long u64;

// SMEM layout (dynamic), bytes:
//   [0      , 65536 )  keys   u64[8192]
//   [65536  , 131072)  hist   u32[16384]   (ALIAS: dies before boxes written)
//   [65536  , 161536)  boxes  float4[6000] (primed: z=x2+1, w=y2+1)
//   [161536 , 185536)  areas  float[6000]  (reference form)
//   [185536 , 190336)  kbox   float4[300]
//   [190336 , 191536)  karea  float[300]
//   [191536 , 192048)  rows   u64[64]
//   [192048 , 192112)  dead   uchar[64]
#define SM_KEYS   0
#define SM_HIST   65536
#define SM_BOXES  65536
#define SM_AREAS  161536
#define SM_KBOX   185536
#define SM_KAREA  190336
#define SM_ROWS   191536
#define SM_DEAD   192048
#define SM_TOTAL  192112

// Precomputed generate_anchors(base=16, ratios={0.5,1,2}, scales={8,16,32})
__constant__ float c_anchors[A_NUM * 4] = {
    -84.f,  -40.f,   99.f,   55.f,
   -176.f,  -88.f,  191.f,  103.f,
   -360.f, -184.f,  375.f,  199.f,
    -56.f,  -56.f,   71.f,   71.f,
   -120.f, -120.f,  135.f,  135.f,
   -248.f, -248.f,  263.f,  263.f,
    -36.f,  -80.f,   51.f,   95.f,
    -80.f, -168.f,   95.f,  183.f,
   -168.f, -344.f,  183.f,  359.f
};

// Descending value-bucket: monotone non-decreasing in descending-score order;
// coarse order exact, within-bucket order fixed by the full 46-bit key.
__device__ __forceinline__ int score_bucket(float sc) {
    int f = (int)(sc * (float)NBUCKET);
    f = min(max(f, 0), NBUCKET - 1);
    return (NBUCKET - 1) - f;
}

// Guard-banded IoU > 0.7 on PRIMED boxes (z=x2+1, w=y2+1). iw/ih bit-identical
// to reference (fl monotone: min(fl(a+1),fl(b+1)) == fl(min(a,b)+1)); areas
// are reference-form, so the exact fallback divides identical values.
__device__ __forceinline__ bool iou_sup(float4 p, float ap, float4 q, float aq) {
    float iw = fminf(p.z, q.z) - fmaxf(p.x, q.x);
    float ih = fminf(p.w, q.w) - fmaxf(p.y, q.y);
    float inter = fmaxf(iw, 0.0f) * fmaxf(ih, 0.0f);
    float u = ap + aq - inter;
    float diff = inter - NMS_TH * u;
    if (fabsf(diff) > 1e-5f * u) return diff > 0.0f;
    return (inter / u) > NMS_TH;
}

__global__ void __launch_bounds__(NTHREADS, 1)
proposal_kernel(const float* __restrict__ scores,
                const float* __restrict__ deltas,
                const float* __restrict__ im_info,
                float* __restrict__ out)
{
    const unsigned FULL = 0xFFFFFFFFu;
    int b = blockIdx.x;
    int t = threadIdx.x;
    extern __shared__ unsigned char sm[];
    u64*           keys  = (u64*)(sm + SM_KEYS);
    unsigned*      hist  = (unsigned*)(sm + SM_HIST);
    float4*        boxes = (float4*)(sm + SM_BOXES);
    float*         areas = (float*)(sm + SM_AREAS);
    float4*        kbox  = (float4*)(sm + SM_KBOX);
    float*         karea = (float*)(sm + SM_KAREA);
    u64*           rows  = (u64*)(sm + SM_ROWS);
    unsigned char* dead  = (unsigned char*)(sm + SM_DEAD);
    volatile unsigned char* vdead = (volatile unsigned char*)dead;
    __shared__ int s_Bstar, s_cnt;
    __shared__ typename cub::BlockScan<unsigned, NTHREADS>::TempStorage scan_ts;

    // Pre-fill output rows: [b, 0,0,0,0] (d_out arrives poisoned).
    for (int j = t; j < POST_TOPN * 5; j += NTHREADS) {
        int r = j / 5, cc = j % 5;
        out[((size_t)b * POST_TOPN + r) * 5 + cc] = (cc == 0) ? (float)b : 0.0f;
    }

    // ===================== Phase 1: select top-6000 =========================
    if (t == 0) s_Bstar = -1;
    {   // vectorized init: hist zero + keys ~0
        uint4 z4 = make_uint4(0, 0, 0, 0);
        uint4 f4 = make_uint4(~0u, ~0u, ~0u, ~0u);
        uint4* h4 = (uint4*)hist;
        uint4* k4 = (uint4*)keys;
        for (int q = t; q < NBUCKET / 4; q += NTHREADS) h4[q] = z4;
        for (int q = t; q < CAP * 2 / 4; q += NTHREADS) k4[q] = f4;
    }
    __syncthreads();

    const float*  sc_base = scores + ((size_t)b * 2 * A_NUM + A_NUM) * HW_DIM;
    const float4* sc4     = (const float4*)sc_base;     // 16B-aligned, 8550 vecs
    const int     bktT    = score_bucket(SC_THRESH);

    // Pass A (attempt 0: only buckets < bktT, ~7.2K atomics; attempt 1 =
    // fail-closed full fallback, never taken for in-distribution inputs).
    for (int attempt = 0; attempt < 2; attempt++) {
        for (int m4 = t; m4 < N_ANCH / 4; m4 += NTHREADS) {
            float4 s = sc4[m4];
            float sv[4] = {s.x, s.y, s.z, s.w};
            #pragma unroll
            for (int e = 0; e < 4; e++) {
                int bkt = score_bucket(sv[e]);
                if (attempt == 1 || bkt < bktT) atomicAdd(&hist[bkt], 1u);
            }
        }
        __syncthreads();

        // Exclusive scan over buckets; find cutoff bucket B*.
        unsigned cnt16[16], sum = 0;
        #pragma unroll
        for (int k = 0; k < 16; k++) { cnt16[k] = hist[t*16+k]; sum += cnt16[k]; }
        unsigned ex_base;
        cub::BlockScan<unsigned, NTHREADS>(scan_ts).ExclusiveSum(sum, ex_base);
        unsigned run = ex_base;
        #pragma unroll
        for (int k = 0; k < 16; k++) {
            unsigned inc = run + cnt16[k];
            int q = t * 16 + k;
            // crossing only trustworthy where counts are exact
            if (run < PRE_TOPN && inc >= PRE_TOPN && (attempt == 1 || q < bktT))
                s_Bstar = q;
            hist[q] = run;
            run = inc;
        }
        __syncthreads();
        if (s_Bstar >= 0) break;

        // fallback: re-zero hist and recount everything
        uint4 z4 = make_uint4(0, 0, 0, 0);
        uint4* h4 = (uint4*)hist;
        for (int q = t; q < NBUCKET / 4; q += NTHREADS) h4[q] = z4;
        __syncthreads();
    }
    int Bstar = s_Bstar;

    // Pass B: scatter selected keys to their global-rank slot (float4 loads).
    for (int m4 = t; m4 < N_ANCH / 4; m4 += NTHREADS) {
        float4 s = sc4[m4];
        float sv[4] = {s.x, s.y, s.z, s.w};
        #pragma unroll
        for (int e = 0; e < 4; e++) {
            int bkt = score_bucket(sv[e]);
            if (bkt <= Bstar) {
                int m = m4 * 4 + e;
                unsigned u = __float_as_uint(sv[e]);
                u = min(u, 0x3F7FFFFFu);
                unsigned d = 0x3F7FFFFFu - u;
                int a = m / HW_DIM, hw = m - a * HW_DIM;
                unsigned idx = (unsigned)(hw * A_NUM + a);   // reference flatten
                int slot = (int)atomicAdd(&hist[bkt], 1u);
                if (slot < CAP) keys[slot] = ((u64)d << 16) | idx;
            }
        }
    }
    __syncthreads();

    // Per-bucket insertion sort by full key (spans ~Poisson(2.1)).
    for (int q = t; q <= Bstar; q += NTHREADS) {
        int start = (q == 0) ? 0 : (int)hist[q - 1];
        int end   = (int)hist[q];
        if (end > CAP) end = CAP;
        for (int x = start + 1; x < end; x++) {
            u64 kx = keys[x];
            int y = x - 1;
            while (y >= start && keys[y] > kx) { keys[y + 1] = keys[y]; y--; }
            keys[y + 1] = kx;
        }
    }
    __syncthreads();   // hist dead from here; boxes region may be written

    // ===================== Phase 2: decode into SMEM ========================
    float imh = im_info[b * 3 + 0];
    float imw = im_info[b * 3 + 1];
    const float* dl = deltas + (size_t)b * 4 * A_NUM * HW_DIM;

    for (int p = t; p < PRE_TOPN; p += NTHREADS) {
        unsigned idx = (unsigned)(keys[p] & 0xFFFFull);
        int a  = idx % A_NUM;
        int hw = idx / A_NUM;
        int w  = hw % W_DIM;
        int h  = hw / W_DIM;

        float sx = (float)(w * 16);
        float sy = (float)(h * 16);
        float ax1 = c_anchors[a * 4 + 0] + sx;
        float ay1 = c_anchors[a * 4 + 1] + sy;
        float ax2 = c_anchors[a * 4 + 2] + sx;
        float ay2 = c_anchors[a * 4 + 3] + sy;

        float wa  = ax2 - ax1 + 1.0f;
        float ha  = ay2 - ay1 + 1.0f;
        float cxa = ax1 + 0.5f * wa;
        float cya = ay1 + 0.5f * ha;

        size_t dbase = (size_t)(a * 4) * HW_DIM + hw;
        float dx = dl[dbase];
        float dy = dl[dbase +     HW_DIM];
        float dw = dl[dbase + 2 * HW_DIM];
        float dh = dl[dbase + 3 * HW_DIM];

        float pcx = dx * wa + cxa;
        float pcy = dy * ha + cya;
        float pw  = expf(dw) * wa;
        float ph  = expf(dh) * ha;

        float x1 = fminf(fmaxf(pcx - 0.5f * pw, 0.0f), imw - 1.0f);
        float y1 = fminf(fmaxf(pcy - 0.5f * ph, 0.0f), imh - 1.0f);
        float x2 = fminf(fmaxf(pcx + 0.5f * pw, 0.0f), imw - 1.0f);
        float y2 = fminf(fmaxf(pcy + 0.5f * ph, 0.0f), imh - 1.0f);

        // reference-form area FIRST, then primed box (monotone-rounded +1)
        areas[p] = (x2 - x1 + 1.0f) * (y2 - y1 + 1.0f);
        boxes[p] = make_float4(x1, y1, x2 + 1.0f, y2 + 1.0f);
    }
    if (t == 0) s_cnt = 0;
    __syncthreads();

    // ===================== Phase 3: chunked greedy NMS [R13 form] ===========
    // Chunk c = candidates [c*64, c*64+64). Suppressed iff IoU>0.7 with an
    // earlier kept box: earlier chunks -> kept-list test (12 groups x 64, with
    // cross-group early-abort via dead[] polling); same chunk -> 64x64 matrix
    // (4 threads/row, shfl-combined, overlapped with kept-test) + t0
    // bit-propagation. Exactly reproduces greedy NMS order.
    for (int c = 0; c < NCHUNK; c++) {
        int base   = c * 64;
        int nvalid = min(64, PRE_TOPN - base);
        if (t < 64) dead[t] = (t >= nvalid) ? 1 : 0;
        __syncthreads();                       // S1: dead reset + s_cnt visible
        int kc = s_cnt;

        if (t >= 256) {
            // kept-test: 12 groups of 64; group g tests kept indices
            // g, g+12, g+24, ... for candidate j = (t-256)&63; dead[] poll
            // software-pipelined ahead of each IoU for cross-group abort.
            int j   = (t - 256) & 63;
            int grp = (t - 256) >> 6;
            if (j < nvalid && kc > 0) {
                float4 bj = boxes[base + j];
                float  aj = areas[base + j];
                for (int k = grp; k < kc; k += KGROUPS) {
                    unsigned char d = vdead[j];          // overlaps IoU math
                    if (iou_sup(kbox[k], karea[k], bj, aj)) { dead[j] = 1; break; }
                    if (d) break;
                }
            }
        } else {
            // intra-chunk matrix: 4 threads per row, strided columns,
            // OR-combined via shfl_xor (lanes row*4+sub within each warp)
            int sub = t & 3;
            int row = t >> 2;                  // 0..63
            u64 bits = 0;
            if (row < nvalid) {
                float4 b1 = boxes[base + row];
                float  a1 = areas[base + row];
                for (int j2 = row + 1 + sub; j2 < nvalid; j2 += 4) {
                    if (iou_sup(b1, a1, boxes[base + j2], areas[base + j2]))
                        bits |= 1ull << j2;
                }
            }
            bits |= __shfl_xor_sync(FULL, bits, 1);
            bits |= __shfl_xor_sync(FULL, bits, 2);
            if (sub == 0 && row < 64) rows[row] = bits;
        }
        __syncthreads();                       // S2

        if (t < 32) {
            unsigned lo = __ballot_sync(FULL, dead[t]      == 0);
            unsigned hi = __ballot_sync(FULL, dead[t + 32] == 0);
            if (t == 0) {
                u64 alive = (u64)lo | ((u64)hi << 32);
                int cnt = s_cnt;
                while (alive && cnt < POST_TOPN) {
                    int j = __ffsll((long long)alive) - 1;
                    kbox[cnt]  = boxes[base + j];
                    karea[cnt] = areas[base + j];
                    cnt++;
                    alive &= ~(rows[j] | (1ull << j));
                }
                s_cnt = cnt;
            }
        }
        __syncthreads();                       // S3
        if (s_cnt >= POST_TOPN) break;
    }

    // ===================== Emit kept boxes (un-prime x2,y2) =================
    int total = s_cnt;
    for (int k = t; k < total; k += NTHREADS) {
        float4 v = kbox[k];
        float* o = out + ((size_t)b * POST_TOPN + k) * 5;
        o[1] = v.x; o[2] = v.y; o[3] = v.z - 1.0f; o[4] = v.w - 1.0f;
    }
}

// ---------------------------------------------------------------------------
// Launch: ONE kernel, one CTA per image.
// ---------------------------------------------------------------------------
extern "C" void kernel_launch(void* const* d_in, const int* in_sizes, int n_in,
                              void* d_out, int out_size)
{
    const float* scores  = (const float*)d_in[0];   // (4, 18, 50, 76)
    const float* deltas  = (const float*)d_in[1];   // (4, 36, 50, 76)
    const float* im_info = (const float*)d_in[2];   // (4, 3)
    float*       out     = (float*)d_out;           // (4, 300, 5)

    cudaFuncSetAttribute(proposal_kernel,
                         cudaFuncAttributeMaxDynamicSharedMemorySize,
                         SM_TOTAL);
    proposal_kernel<<<BATCH, NTHREADS, SM_TOTAL>>>(scores, deltas, im_info, out);
}

// round 17
// speedup vs baseline: 1.6099x; 1.0088x over previous
#include <cuda_runtime.h>
#include <cstdint>
#include <cub/cub.cuh>

// ---------------------------------------------------------------------------
// ProposalLayer: B=4, A=9, H=50, W=76, FEAT_STRIDE=16
// pre-NMS topN = 6000, post-NMS topN = 300, nms thresh = 0.7
// R16 = R15 (84.0us) with a leaner NMS loop:
//   - double-buffered dead[] flags: next chunk's reset is done during the
//     current chunk's compute phase -> 2 barriers per chunk instead of 3
//   - kept-test unrolled 2x (one dead-poll per pair) to shorten the serial
//     chain for surviving candidates
// Everything else (select, decode, IoU arithmetic) bit-identical to R15.
// ---------------------------------------------------------------------------

#define BATCH     4
#define A_NUM     9
#define H_DIM     50
#define W_DIM     76
#define HW_DIM    (H_DIM * W_DIM)          // 3800
#define N_ANCH    (A_NUM * HW_DIM)         // 34200 (= 8550 float4, 16B-aligned)
#define PRE_TOPN  6000
#define POST_TOPN 300
#define NMS_TH    0.7f
#define NBUCKET   16384
#define CAP       8192
#define NTHREADS  1024
#define NCHUNK    94                        // ceil(6000/64)
#define KGROUPS   12                        // kept-test groups (768 threads)
#define SC_THRESH 0.79f                     // conservative top-6000 cutoff guess

typedef unsigned long long u64;

// SMEM layout (dynamic), bytes:
//   [0      , 65536 )  keys   u64[8192]
//   [65536  , 131072)  hist   u32[16384]   (ALIAS: dies before boxes written)
//   [65536  , 161536)  boxes  float4[6000] (primed: z=x2+1, w=y2+1)
//   [161536 , 185536)  areas  float[6000]  (reference form)
//   [185536 , 190336)  kbox   float4[300]
//   [190336 , 191536)  karea  float[300]
//   [191536 , 192048)  rows   u64[64]
//   [192048 , 192112)  dead0  uchar[64]
//   [192112 , 192176)  dead1  uchar[64]
#define SM_KEYS   0
#define SM_HIST   65536
#define SM_BOXES  65536
#define SM_AREAS  161536
#define SM_KBOX   185536
#define SM_KAREA  190336
#define SM_ROWS   191536
#define SM_DEAD0  192048
#define SM_DEAD1  192112
#define SM_TOTAL  192176

// Precomputed generate_anchors(base=16, ratios={0.5,1,2}, scales={8,16,32})
__constant__ float c_anchors[A_NUM * 4] = {
    -84.f,  -40.f,   99.f,   55.f,
   -176.f,  -88.f,  191.f,  103.f,
   -360.f, -184.f,  375.f,  199.f,
    -56.f,  -56.f,   71.f,   71.f,
   -120.f, -120.f,  135.f,  135.f,
   -248.f, -248.f,  263.f,  263.f,
    -36.f,  -80.f,   51.f,   95.f,
    -80.f, -168.f,   95.f,  183.f,
   -168.f, -344.f,  183.f,  359.f
};

// Descending value-bucket: monotone non-decreasing in descending-score order;
// coarse order exact, within-bucket order fixed by the full 46-bit key.
__device__ __forceinline__ int score_bucket(float sc) {
    int f = (int)(sc * (float)NBUCKET);
    f = min(max(f, 0), NBUCKET - 1);
    return (NBUCKET - 1) - f;
}

// Guard-banded IoU > 0.7 on PRIMED boxes (z=x2+1, w=y2+1). iw/ih bit-identical
// to reference (fl monotone: min(fl(a+1),fl(b+1)) == fl(min(a,b)+1)); areas
// are reference-form, so the exact fallback divides identical values.
__device__ __forceinline__ bool iou_sup(float4 p, float ap, float4 q, float aq) {
    float iw = fminf(p.z, q.z) - fmaxf(p.x, q.x);
    float ih = fminf(p.w, q.w) - fmaxf(p.y, q.y);
    float inter = fmaxf(iw, 0.0f) * fmaxf(ih, 0.0f);
    float u = ap + aq - inter;
    float diff = inter - NMS_TH * u;
    if (fabsf(diff) > 1e-5f * u) return diff > 0.0f;
    return (inter / u) > NMS_TH;
}

__global__ void __launch_bounds__(NTHREADS, 1)
proposal_kernel(const float* __restrict__ scores,
                const float* __restrict__ deltas,
                const float* __restrict__ im_info,
                float* __restrict__ out)
{
    const unsigned FULL = 0xFFFFFFFFu;
    int b = blockIdx.x;
    int t = threadIdx.x;
    extern __shared__ unsigned char sm[];
    u64*           keys  = (u64*)(sm + SM_KEYS);
    unsigned*      hist  = (unsigned*)(sm + SM_HIST);
    float4*        boxes = (float4*)(sm + SM_BOXES);
    float*         areas = (float*)(sm + SM_AREAS);
    float4*        kbox  = (float4*)(sm + SM_KBOX);
    float*         karea = (float*)(sm + SM_KAREA);
    u64*           rows  = (u64*)(sm + SM_ROWS);
    unsigned char* dead0 = (unsigned char*)(sm + SM_DEAD0);
    unsigned char* dead1 = (unsigned char*)(sm + SM_DEAD1);
    __shared__ int s_Bstar, s_cnt;
    __shared__ typename cub::BlockScan<unsigned, NTHREADS>::TempStorage scan_ts;

    // Pre-fill output rows: [b, 0,0,0,0] (d_out arrives poisoned).
    for (int j = t; j < POST_TOPN * 5; j += NTHREADS) {
        int r = j / 5, cc = j % 5;
        out[((size_t)b * POST_TOPN + r) * 5 + cc] = (cc == 0) ? (float)b : 0.0f;
    }

    // ===================== Phase 1: select top-6000 =========================
    if (t == 0) s_Bstar = -1;
    {   // vectorized init: hist zero + keys ~0
        uint4 z4 = make_uint4(0, 0, 0, 0);
        uint4 f4 = make_uint4(~0u, ~0u, ~0u, ~0u);
        uint4* h4 = (uint4*)hist;
        uint4* k4 = (uint4*)keys;
        for (int q = t; q < NBUCKET / 4; q += NTHREADS) h4[q] = z4;
        for (int q = t; q < CAP * 2 / 4; q += NTHREADS) k4[q] = f4;
    }
    __syncthreads();

    const float*  sc_base = scores + ((size_t)b * 2 * A_NUM + A_NUM) * HW_DIM;
    const float4* sc4     = (const float4*)sc_base;     // 16B-aligned, 8550 vecs
    const int     bktT    = score_bucket(SC_THRESH);

    // Pass A (attempt 0: only buckets < bktT; attempt 1 = fail-closed full
    // fallback, never taken for in-distribution inputs).
    for (int attempt = 0; attempt < 2; attempt++) {
        for (int m4 = t; m4 < N_ANCH / 4; m4 += NTHREADS) {
            float4 s = sc4[m4];
            float sv[4] = {s.x, s.y, s.z, s.w};
            #pragma unroll
            for (int e = 0; e < 4; e++) {
                int bkt = score_bucket(sv[e]);
                if (attempt == 1 || bkt < bktT) atomicAdd(&hist[bkt], 1u);
            }
        }
        __syncthreads();

        // Exclusive scan over buckets; find cutoff bucket B*.
        unsigned cnt16[16], sum = 0;
        #pragma unroll
        for (int k = 0; k < 16; k++) { cnt16[k] = hist[t*16+k]; sum += cnt16[k]; }
        unsigned ex_base;
        cub::BlockScan<unsigned, NTHREADS>(scan_ts).ExclusiveSum(sum, ex_base);
        unsigned run = ex_base;
        #pragma unroll
        for (int k = 0; k < 16; k++) {
            unsigned inc = run + cnt16[k];
            int q = t * 16 + k;
            if (run < PRE_TOPN && inc >= PRE_TOPN && (attempt == 1 || q < bktT))
                s_Bstar = q;
            hist[q] = run;
            run = inc;
        }
        __syncthreads();
        if (s_Bstar >= 0) break;

        // fallback: re-zero hist and recount everything
        uint4 z4 = make_uint4(0, 0, 0, 0);
        uint4* h4 = (uint4*)hist;
        for (int q = t; q < NBUCKET / 4; q += NTHREADS) h4[q] = z4;
        __syncthreads();
    }
    int Bstar = s_Bstar;

    // Pass B: scatter selected keys to their global-rank slot (float4 loads).
    for (int m4 = t; m4 < N_ANCH / 4; m4 += NTHREADS) {
        float4 s = sc4[m4];
        float sv[4] = {s.x, s.y, s.z, s.w};
        #pragma unroll
        for (int e = 0; e < 4; e++) {
            int bkt = score_bucket(sv[e]);
            if (bkt <= Bstar) {
                int m = m4 * 4 + e;
                unsigned u = __float_as_uint(sv[e]);
                u = min(u, 0x3F7FFFFFu);
                unsigned d = 0x3F7FFFFFu - u;
                int a = m / HW_DIM, hw = m - a * HW_DIM;
                unsigned idx = (unsigned)(hw * A_NUM + a);   // reference flatten
                int slot = (int)atomicAdd(&hist[bkt], 1u);
                if (slot < CAP) keys[slot] = ((u64)d << 16) | idx;
            }
        }
    }
    __syncthreads();

    // Per-bucket insertion sort by full key (spans ~Poisson(2.1)).
    for (int q = t; q <= Bstar; q += NTHREADS) {
        int start = (q == 0) ? 0 : (int)hist[q - 1];
        int end   = (int)hist[q];
        if (end > CAP) end = CAP;
        for (int x = start + 1; x < end; x++) {
            u64 kx = keys[x];
            int y = x - 1;
            while (y >= start && keys[y] > kx) { keys[y + 1] = keys[y]; y--; }
            keys[y + 1] = kx;
        }
    }
    __syncthreads();   // hist dead from here; boxes region may be written

    // ===================== Phase 2: decode into SMEM ========================
    float imh = im_info[b * 3 + 0];
    float imw = im_info[b * 3 + 1];
    const float* dl = deltas + (size_t)b * 4 * A_NUM * HW_DIM;

    for (int p = t; p < PRE_TOPN; p += NTHREADS) {
        unsigned idx = (unsigned)(keys[p] & 0xFFFFull);
        int a  = idx % A_NUM;
        int hw = idx / A_NUM;
        int w  = hw % W_DIM;
        int h  = hw / W_DIM;

        float sx = (float)(w * 16);
        float sy = (float)(h * 16);
        float ax1 = c_anchors[a * 4 + 0] + sx;
        float ay1 = c_anchors[a * 4 + 1] + sy;
        float ax2 = c_anchors[a * 4 + 2] + sx;
        float ay2 = c_anchors[a * 4 + 3] + sy;

        float wa  = ax2 - ax1 + 1.0f;
        float ha  = ay2 - ay1 + 1.0f;
        float cxa = ax1 + 0.5f * wa;
        float cya = ay1 + 0.5f * ha;

        size_t dbase = (size_t)(a * 4) * HW_DIM + hw;
        float dx = dl[dbase];
        float dy = dl[dbase +     HW_DIM];
        float dw = dl[dbase + 2 * HW_DIM];
        float dh = dl[dbase + 3 * HW_DIM];

        float pcx = dx * wa + cxa;
        float pcy = dy * ha + cya;
        float pw  = expf(dw) * wa;
        float ph  = expf(dh) * ha;

        float x1 = fminf(fmaxf(pcx - 0.5f * pw, 0.0f), imw - 1.0f);
        float y1 = fminf(fmaxf(pcy - 0.5f * ph, 0.0f), imh - 1.0f);
        float x2 = fminf(fmaxf(pcx + 0.5f * pw, 0.0f), imw - 1.0f);
        float y2 = fminf(fmaxf(pcy + 0.5f * ph, 0.0f), imh - 1.0f);

        // reference-form area FIRST, then primed box (monotone-rounded +1)
        areas[p] = (x2 - x1 + 1.0f) * (y2 - y1 + 1.0f);
        boxes[p] = make_float4(x1, y1, x2 + 1.0f, y2 + 1.0f);
    }
    if (t == 0) s_cnt = 0;
    // preset BOTH dead buffers for chunks 0 and 1 (both full 64-wide)
    if (t < 64)                dead0[t]      = 0;
    else if (t < 128)          dead1[t - 64] = 0;
    __syncthreads();

    // ===================== Phase 3: chunked greedy NMS ======================
    // 2 barriers/chunk: compute phase (kept-test + intra-matrix + reset of the
    // OTHER dead buffer for chunk c+1) -> BAR -> ballot/propagate -> BAR.
    int parity = 0;
    for (int c = 0; c < NCHUNK; c++) {
        int base   = c * 64;
        int nvalid = min(64, PRE_TOPN - base);
        unsigned char* dcur  = parity ? dead1 : dead0;
        unsigned char* dnext = parity ? dead0 : dead1;
        volatile unsigned char* vdcur = (volatile unsigned char*)dcur;
        int kc = s_cnt;

        if (t >= 256) {
            // kept-test: 12 groups of 64; group g tests kept g, g+12, ...
            // for candidate j = (t-256)&63; unroll-2 with one poll per pair.
            int j   = (t - 256) & 63;
            int grp = (t - 256) >> 6;
            if (j < nvalid && kc > 0) {
                float4 bj = boxes[base + j];
                float  aj = areas[base + j];
                int k = grp;
                while (k < kc) {
                    unsigned char d = vdcur[j];            // overlaps IoU math
                    if (iou_sup(kbox[k], karea[k], bj, aj)) { dcur[j] = 1; break; }
                    int k2 = k + KGROUPS;
                    if (k2 < kc &&
                        iou_sup(kbox[k2], karea[k2], bj, aj)) { dcur[j] = 1; break; }
                    if (d) break;
                    k = k2 + KGROUPS;
                }
            }
        } else {
            // intra-chunk matrix: 4 threads per row, strided columns,
            // OR-combined via shfl_xor; sub==3 threads also reset dnext
            // for chunk c+1 (deterministic nvalid).
            int sub = t & 3;
            int row = t >> 2;                  // 0..63
            u64 bits = 0;
            if (row < nvalid) {
                float4 b1 = boxes[base + row];
                float  a1 = areas[base + row];
                for (int j2 = row + 1 + sub; j2 < nvalid; j2 += 4) {
                    if (iou_sup(b1, a1, boxes[base + j2], areas[base + j2]))
                        bits |= 1ull << j2;
                }
            }
            bits |= __shfl_xor_sync(FULL, bits, 1);
            bits |= __shfl_xor_sync(FULL, bits, 2);
            if (sub == 0) rows[row] = bits;
            if (sub == 3) {
                int nvn = PRE_TOPN - (base + 64);   // next chunk's valid count
                dnext[row] = (row >= nvn) ? 1 : 0;  // nvn<=0 -> all dead (unused)
            }
        }
        __syncthreads();                       // S2: dead/rows complete

        if (t < 32) {
            unsigned lo = __ballot_sync(FULL, dcur[t]      == 0);
            unsigned hi = __ballot_sync(FULL, dcur[t + 32] == 0);
            if (t == 0) {
                u64 alive = (u64)lo | ((u64)hi << 32);
                int cnt = s_cnt;
                while (alive && cnt < POST_TOPN) {
                    int j = __ffsll((long long)alive) - 1;
                    kbox[cnt]  = boxes[base + j];
                    karea[cnt] = areas[base + j];
                    cnt++;
                    alive &= ~(rows[j] | (1ull << j));
                }
                s_cnt = cnt;
            }
        }
        __syncthreads();                       // S3: s_cnt/kbox visible
        if (s_cnt >= POST_TOPN) break;
        parity ^= 1;
    }

    // ===================== Emit kept boxes (un-prime x2,y2) =================
    int total = s_cnt;
    for (int k = t; k < total; k += NTHREADS) {
        float4 v = kbox[k];
        float* o = out + ((size_t)b * POST_TOPN + k) * 5;
        o[1] = v.x; o[2] = v.y; o[3] = v.z - 1.0f; o[4] = v.w - 1.0f;
    }
}

// ---------------------------------------------------------------------------
// Launch: ONE kernel, one CTA per image.
// ---------------------------------------------------------------------------
extern "C" void kernel_launch(void* const* d_in, const int* in_sizes, int n_in,
                              void* d_out, int out_size)
{
    const float* scores  = (const float*)d_in[0];   // (4, 18, 50, 76)
    const float* deltas  = (const float*)d_in[1];   // (4, 36, 50, 76)
    const float* im_info = (const float*)d_in[2];   // (4, 3)
    float*       out     = (float*)d_out;           // (4, 300, 5)

    cudaFuncSetAttribute(proposal_kernel,
                         cudaFuncAttributeMaxDynamicSharedMemorySize,
                         SM_TOTAL);
    proposal_kernel<<<BATCH, NTHREADS, SM_TOTAL>>>(scores, deltas, im_info, out);
}